// round 17
// baseline (speedup 1.0000x reference)
#include <cuda_runtime.h>
#include <cuda_bf16.h>
#include <cuda_fp16.h>
#include <math.h>
#include <stdint.h>

// Problem constants
constexpr int CB = 2, CS = 2048, CD = 256, CH = 4, CL = 4, CV = 50257, CHD = 64;
constexpr int CM = CB * CS;      // 4096 rows
constexpr int CFF = 4 * CD;      // 1024

// ----------------------------------------------------------------------------
// Scratch (static device globals — no allocation inside kernel_launch)
// ----------------------------------------------------------------------------
__device__ float  g_h[CM * CD];
__device__ __half g_n[CM * CD];
__device__ __half g_q[CM * CD], g_k[CM * CD], g_v[CM * CD];
__device__ __half g_att[CM * CD];
__device__ __half g_m[CM * CFF];
__device__ __half g_tf[(size_t)CV * CD];
__device__ __half g_wq[CL * CD * CD], g_wk[CL * CD * CD];
__device__ __half g_wv[CL * CD * CD], g_wo[CL * CD * CD];
__device__ __half g_w1[CL * CD * CFF], g_w2[CL * CD * CFF];

// ----------------------------------------------------------------------------
// Helpers
// ----------------------------------------------------------------------------
__device__ __forceinline__ uint32_t smem_u32(const void* p) {
    uint32_t a;
    asm("{ .reg .u64 t; cvta.to.shared.u64 t, %1; cvt.u32.u64 %0, t; }"
        : "=r"(a) : "l"(p));
    return a;
}
__device__ __forceinline__ void ldsm4(uint32_t* r, uint32_t addr) {
    asm volatile("ldmatrix.sync.aligned.m8n8.x4.shared.b16 {%0,%1,%2,%3}, [%4];"
                 : "=r"(r[0]), "=r"(r[1]), "=r"(r[2]), "=r"(r[3]) : "r"(addr));
}
__device__ __forceinline__ void ldsm4t(uint32_t* r, uint32_t addr) {
    asm volatile("ldmatrix.sync.aligned.m8n8.x4.trans.shared.b16 {%0,%1,%2,%3}, [%4];"
                 : "=r"(r[0]), "=r"(r[1]), "=r"(r[2]), "=r"(r[3]) : "r"(addr));
}
__device__ __forceinline__ void mma16816h(float* c, const uint32_t* a, const uint32_t* b) {
    asm volatile("mma.sync.aligned.m16n8k16.row.col.f32.f16.f16.f32 "
                 "{%0,%1,%2,%3}, {%4,%5,%6,%7}, {%8,%9}, {%0,%1,%2,%3};"
                 : "+f"(c[0]), "+f"(c[1]), "+f"(c[2]), "+f"(c[3])
                 : "r"(a[0]), "r"(a[1]), "r"(a[2]), "r"(a[3]),
                   "r"(b[0]), "r"(b[1]));
}
__device__ __forceinline__ uint32_t pack_h2(float x, float y) {
    __half2 p = __floats2half2_rn(x, y);
    return *(uint32_t*)&p;
}
__device__ __forceinline__ void cp16(uint32_t dst, const void* src) {
    asm volatile("cp.async.ca.shared.global [%0], [%1], 16;" :: "r"(dst), "l"(src));
}
__device__ __forceinline__ void cp_commit() {
    asm volatile("cp.async.commit_group;" ::: "memory");
}
template <int N>
__device__ __forceinline__ void cp_wait() {
    asm volatile("cp.async.wait_group %0;" :: "n"(N) : "memory");
}

// ----------------------------------------------------------------------------
// One-launch fp32 -> fp16 converter for tok_emb + all weights
// ----------------------------------------------------------------------------
constexpr size_t NP_TOK = (size_t)CV * CD / 2;
constexpr size_t NP_W   = (size_t)CL * CD * CD / 2;
constexpr size_t NP_WF  = (size_t)CL * CD * CFF / 2;
constexpr size_t NP_TOT = NP_TOK + 4 * NP_W + 2 * NP_WF;

__global__ void convert_all_kernel(
    const float* __restrict__ tok, const float* __restrict__ Wq,
    const float* __restrict__ Wk, const float* __restrict__ Wv,
    const float* __restrict__ Wo, const float* __restrict__ W1,
    const float* __restrict__ W2,
    __half* __restrict__ tf, __half* __restrict__ wq, __half* __restrict__ wk,
    __half* __restrict__ wv, __half* __restrict__ wo, __half* __restrict__ w1,
    __half* __restrict__ w2) {
    size_t i = (size_t)blockIdx.x * blockDim.x + threadIdx.x;
    if (i >= NP_TOT) return;
    const float* src; __half* dst;
    if (i < NP_TOK) { src = tok; dst = tf; }
    else {
        i -= NP_TOK;
        if (i < NP_W)          { src = Wq; dst = wq; }
        else if (i < 2 * NP_W) { i -= NP_W;     src = Wk; dst = wk; }
        else if (i < 3 * NP_W) { i -= 2 * NP_W; src = Wv; dst = wv; }
        else if (i < 4 * NP_W) { i -= 3 * NP_W; src = Wo; dst = wo; }
        else if (i < 4 * NP_W + NP_WF) { i -= 4 * NP_W; src = W1; dst = w1; }
        else { i -= 4 * NP_W + NP_WF; src = W2; dst = w2; }
    }
    float2 x = *(const float2*)(src + 2 * i);
    *(__half2*)(dst + 2 * i) = __floats2half2_rn(x.x, x.y);
}

// ----------------------------------------------------------------------------
// Single-term fp16 HMMA GEMM core, MTILE x NTILE x BK, 256 thr.
// 3-stage cp.async ring, one __syncthreads per k-chunk. 2 CTAs/SM.
// TRANSB epilogue: smem-staged, coalesced fp32 stores (N odd).
// ----------------------------------------------------------------------------
template <int MTILE, int NTILE, int BK, bool TRANSB>
struct GCfg {
    static constexpr int WM = MTILE / 64;
    static constexpr int WN = 8 / WM;
    static constexpr int WARP_N = NTILE / WN;
    static constexpr int NI = WARP_N / 8;
    static constexpr int NB2 = WARP_N / 16;
    static constexpr int BPITCH = NTILE * 2 + 16;   // !TRANSB B row pitch (bytes)
    static constexpr int APITCH = BK * 2 + 16;      // A row pitch (bytes)
    static constexpr int ASLOT = MTILE * APITCH;
    static constexpr int BSLOT = TRANSB ? NTILE * APITCH : BK * BPITCH;
    static constexpr int STAGE = ASLOT + BSLOT;
    static constexpr int SMEM = 3 * STAGE;
};

template <int MTILE, int NTILE, int BK, bool TRANSB, bool GELU, bool F16OUT>
__device__ __forceinline__ void hgemm_core(
    const __half* __restrict__ A, const __half* __restrict__ B,
    const float* __restrict__ bias, const float* __restrict__ resid,
    float* __restrict__ C, __half* __restrict__ Of,
    int N, int K, int m0, int n0, char* smbase) {
    using CF = GCfg<MTILE, NTILE, BK, TRANSB>;
    const int t = threadIdx.x;
    const int lane = t & 31, wid = t >> 5;
    const int wm = wid % CF::WM, wn = wid / CF::WM;
    const uint32_t sU = smem_u32(smbase);
    constexpr int KB8 = BK / 8;                     // 16B chunks per A row

    auto load_tile = [&](int s, int kc) {
        const int k0 = kc * BK;
        const uint32_t sb = sU + (uint32_t)(s * CF::STAGE);
        // A: MTILE rows x BK k
#pragma unroll
        for (int i = 0; i < MTILE * KB8 / 256; i++) {
            int e = t + i * 256;
            int row = e / KB8, c = e % KB8;
            cp16(sb + row * CF::APITCH + c * 16,
                 A + (size_t)(m0 + row) * K + k0 + c * 8);
        }
        // B
        if (!TRANSB) {                    // BK k-rows x NTILE
            constexpr int OPS = BK * NTILE / 8;
#pragma unroll
            for (int i = 0; i < OPS / 256; i++) {
                int e = t + i * 256;
                int row = e / (NTILE / 8), c = e % (NTILE / 8);
                cp16(sb + CF::ASLOT + row * CF::BPITCH + c * 16,
                     B + (size_t)(k0 + row) * N + n0 + c * 8);
            }
        } else {                          // NTILE n-rows x BK k
#pragma unroll
            for (int i = 0; i < NTILE * KB8 / 256; i++) {
                int e = t + i * 256;
                int row = e / KB8, c = e % KB8;
                int nr = n0 + row;
                if (nr >= N) nr = 0;
                cp16(sb + CF::ASLOT + row * CF::APITCH + c * 16,
                     B + (size_t)nr * K + k0 + c * 8);
            }
        }
        cp_commit();
    };

    const uint32_t aoff =
        (uint32_t)((wm * 64 + (lane & 7) + ((lane >> 3) & 1) * 8) * CF::APITCH +
                   (lane >> 4) * 16);
    uint32_t boff;
    if (!TRANSB)
        boff = (uint32_t)(((lane & 7) + ((lane >> 3) & 1) * 8) * CF::BPITCH +
                          (wn * CF::WARP_N + (lane >> 4) * 8) * 2);
    else
        boff = (uint32_t)((wn * CF::WARP_N + (lane & 7) + (lane >> 4) * 8) * CF::APITCH +
                          ((lane >> 3) & 1) * 16);

    float acc[4][CF::NI][4] = {};
    const int KT = K / BK;

    load_tile(0, 0);
    if (KT > 1) load_tile(1, 1);

    int stage = 0;
    for (int kc = 0; kc < KT; kc++) {
        if (kc + 1 < KT) cp_wait<1>(); else cp_wait<0>();
        __syncthreads();
        if (kc + 2 < KT) {
            int s2 = stage + 2; if (s2 >= 3) s2 -= 3;
            load_tile(s2, kc + 2);
        }
        const uint32_t sb = sU + (uint32_t)(stage * CF::STAGE);
#pragma unroll
        for (int ks = 0; ks < BK / 16; ks++) {
            uint32_t ah[4][4], bh[CF::NB2][4];
#pragma unroll
            for (int mi = 0; mi < 4; mi++)
                ldsm4(ah[mi], sb + aoff + mi * (16 * CF::APITCH) + ks * 32);
#pragma unroll
            for (int n2 = 0; n2 < CF::NB2; n2++) {
                if (!TRANSB)
                    ldsm4t(bh[n2], sb + CF::ASLOT + boff + n2 * 32 + ks * (16 * CF::BPITCH));
                else
                    ldsm4(bh[n2], sb + CF::ASLOT + boff + n2 * (16 * CF::APITCH) + ks * 32);
            }
#pragma unroll
            for (int mi = 0; mi < 4; mi++)
#pragma unroll
                for (int ni = 0; ni < CF::NI; ni++)
                    mma16816h(acc[mi][ni], ah[mi], &bh[ni >> 1][(ni & 1) * 2]);
        }
        if (++stage == 3) stage = 0;
    }

    if (TRANSB) {
        // Staged, coalesced fp32 epilogue (lm_head; MTILE=128, NTILE=128)
        constexpr int PIT = 132;
        float* stg = (float*)smbase;
        __syncthreads();
#pragma unroll
        for (int mi = 0; mi < 4; mi++) {
            int lr = wm * 64 + mi * 16 + (lane >> 2);
#pragma unroll
            for (int ni = 0; ni < CF::NI; ni++) {
                int lc = wn * CF::WARP_N + ni * 8 + (lane & 3) * 2;
                stg[lr * PIT + lc]           = acc[mi][ni][0];
                stg[lr * PIT + lc + 1]       = acc[mi][ni][1];
                stg[(lr + 8) * PIT + lc]     = acc[mi][ni][2];
                stg[(lr + 8) * PIT + lc + 1] = acc[mi][ni][3];
            }
        }
        __syncthreads();
#pragma unroll 4
        for (int i = 0; i < (MTILE * NTILE) / 256; i++) {
            int e = t + i * 256;
            int row = e / NTILE, col = e % NTILE;
            int gn = n0 + col;
            if (gn < N)
                C[(size_t)(m0 + row) * N + gn] = stg[row * PIT + col];
        }
        return;
    }

    // Direct epilogue (non-TRANSB)
#pragma unroll
    for (int mi = 0; mi < 4; mi++) {
        const int r0 = m0 + wm * 64 + mi * 16 + (lane >> 2);
#pragma unroll
        for (int ni = 0; ni < CF::NI; ni++) {
            const int col = n0 + wn * CF::WARP_N + ni * 8 + (lane & 3) * 2;
            float v0 = acc[mi][ni][0], v1 = acc[mi][ni][1];
            float v2 = acc[mi][ni][2], v3 = acc[mi][ni][3];
            if (bias) {
                float b0 = bias[col], b1 = bias[col + 1];
                v0 += b0; v1 += b1; v2 += b0; v3 += b1;
            }
            if (GELU) {
                v0 = 0.5f * v0 * (1.f + erff(v0 * 0.70710678118654752f));
                v1 = 0.5f * v1 * (1.f + erff(v1 * 0.70710678118654752f));
                v2 = 0.5f * v2 * (1.f + erff(v2 * 0.70710678118654752f));
                v3 = 0.5f * v3 * (1.f + erff(v3 * 0.70710678118654752f));
            }
            size_t o0 = (size_t)r0 * N + col;
            size_t o1 = o0 + (size_t)8 * N;
            if (F16OUT) {
                *(uint32_t*)(Of + o0) = pack_h2(v0, v1);
                *(uint32_t*)(Of + o1) = pack_h2(v2, v3);
            } else {
                if (resid) {
                    float2 rr0 = *(const float2*)(resid + o0);
                    float2 rr1 = *(const float2*)(resid + o1);
                    v0 += rr0.x; v1 += rr0.y; v2 += rr1.x; v3 += rr1.y;
                }
                *(float2*)(C + o0) = make_float2(v0, v1);
                *(float2*)(C + o1) = make_float2(v2, v3);
            }
        }
    }
}

// Wo / W2: 128x64 BK32, fp32 + residual, 2 CTAs/SM
constexpr int SMEM_RES = GCfg<128, 64, 32, false>::SMEM;
__global__ __launch_bounds__(256, 2)
void gemm_res_kernel(const __half* __restrict__ A, const __half* __restrict__ B,
                     const float* __restrict__ bias, const float* __restrict__ resid,
                     float* __restrict__ C, int N, int K) {
    extern __shared__ char sm[];
    hgemm_core<128, 64, 32, false, false, false>(A, B, bias, resid, C, nullptr,
                                                 N, K, blockIdx.y * 128,
                                                 blockIdx.x * 64, sm);
}

// W1: 128x128 BK32, GELU + fp16 out, 2 CTAs/SM
constexpr int SMEM_BIG = GCfg<128, 128, 32, false>::SMEM;
__global__ __launch_bounds__(256, 2)
void gemm_gelu_kernel(const __half* __restrict__ A, const __half* __restrict__ B,
                      const float* __restrict__ bias, __half* __restrict__ Of,
                      int N, int K) {
    extern __shared__ char sm[];
    hgemm_core<128, 128, 32, false, true, true>(A, B, bias, nullptr, nullptr, Of,
                                                N, K, blockIdx.y * 128,
                                                blockIdx.x * 128, sm);
}

// QKV fused: 128x128 BK32, fp16 out, 2 CTAs/SM
__global__ __launch_bounds__(256, 2)
void qkv_kernel(const __half* __restrict__ A,
                const __half* __restrict__ W0, const __half* __restrict__ W1_,
                const __half* __restrict__ W2_,
                const float* __restrict__ c0, const float* __restrict__ c1,
                const float* __restrict__ c2,
                __half* __restrict__ q, __half* __restrict__ k,
                __half* __restrict__ v) {
    extern __shared__ char sm[];
    int z = blockIdx.z;
    const __half* B = (z == 0) ? W0 : (z == 1) ? W1_ : W2_;
    const float* bi = (z == 0) ? c0 : (z == 1) ? c1 : c2;
    __half* Of = (z == 0) ? q : (z == 1) ? k : v;
    hgemm_core<128, 128, 32, false, false, true>(A, B, bi, nullptr, nullptr, Of,
                                                 CD, CD, blockIdx.y * 128,
                                                 blockIdx.x * 128, sm);
}

// lm_head: 128x128 BK64, TRANSB, staged coalesced fp32 out, m-fast, 2 CTAs/SM
constexpr int SMEM_LMH = GCfg<128, 128, 64, true>::SMEM;
__global__ __launch_bounds__(256, 2)
void lmhead_kernel(const __half* __restrict__ A, const __half* __restrict__ T,
                   float* __restrict__ out) {
    extern __shared__ char sm[];
    hgemm_core<128, 128, 64, true, false, false>(A, T, nullptr, nullptr, out,
                                                 nullptr, CV, CD,
                                                 blockIdx.x * 128,
                                                 blockIdx.y * 128, sm);
}

// ----------------------------------------------------------------------------
// fp16 HMMA flash attention, UNFOLDED: grid (32, B*H), 128 threads, one q-tile
// per CTA (variable KV count). 46 KB smem, 2 CTAs/SM.
// ----------------------------------------------------------------------------
constexpr int AP = 72;
constexpr int TILEB = 64 * AP * 2;
constexpr int ATTN_SMEM = 5 * TILEB;

__global__ __launch_bounds__(128, 2)
void attn_kernel(const __half* __restrict__ Q, const __half* __restrict__ Km,
                 const __half* __restrict__ Vm, __half* __restrict__ At) {
    extern __shared__ char sm[];
    const uint32_t smU = smem_u32(sm);
    const uint32_t qU = smU;
    const uint32_t kvU = smU + TILEB;

    const int t = threadIdx.x;
    const int lane = t & 31, w = t >> 5;
    const int bh = blockIdx.y;
    const int b = bh >> 2, h = bh & 3;
    const size_t base = (size_t)b * CS * CD + (size_t)h * CHD;
    const int qt = blockIdx.x;
    const int q0 = qt * 64;

    auto load_kv = [&](int buf, int kt) {
        const int k0 = kt * 64;
#pragma unroll
        for (int a = 0; a < 2; a++) {
            const __half* src = (a ? Vm : Km) + base + (size_t)k0 * CD;
            const uint32_t dbase = kvU + (buf * 2 + a) * TILEB;
#pragma unroll
            for (int i = 0; i < 4; i++) {
                int e = t + i * 128;
                int row = e >> 3, c = e & 7;
                cp16(dbase + row * (AP * 2) + c * 16, src + (size_t)row * CD + c * 8);
            }
        }
        cp_commit();
    };

    load_kv(0, 0);
    {
        const __half* src = Q + base + (size_t)q0 * CD;
#pragma unroll
        for (int i = 0; i < 4; i++) {
            int e = t + i * 128;
            int row = e >> 3, c = e & 7;
            *(uint4*)(sm + row * (AP * 2) + c * 16) =
                *(const uint4*)(src + (size_t)row * CD + c * 8);
        }
    }
    __syncthreads();

    uint32_t qf[4][4];
    {
        const uint32_t aoff =
            (uint32_t)((w * 16 + (lane & 7) + ((lane >> 3) & 1) * 8) * (AP * 2) +
                       (lane >> 4) * 16);
#pragma unroll
        for (int ks = 0; ks < 4; ks++)
            ldsm4(qf[ks], qU + aoff + ks * 32);
    }

    float acc[8][4] = {};
    float m_0 = -1e30f, m_1 = -1e30f, l_0 = 0.f, l_1 = 0.f;
    const int rl0 = w * 16 + (lane >> 2);

    for (int kt = 0; kt <= qt; kt++) {
        const int buf = kt & 1;
        const bool more = kt < qt;
        if (more) { load_kv(buf ^ 1, kt + 1); cp_wait<1>(); }
        else      { cp_wait<0>(); }
        __syncthreads();

        const uint32_t kBuf = kvU + (buf * 2 + 0) * TILEB;
        const uint32_t vBuf = kvU + (buf * 2 + 1) * TILEB;

        float st[8][4] = {};
#pragma unroll
        for (int ks = 0; ks < 4; ks++) {
            uint32_t kf[4][4];
#pragma unroll
            for (int nt = 0; nt < 4; nt++) {
                uint32_t ko =
                    (uint32_t)((nt * 16 + (lane & 7) + (lane >> 4) * 8) * (AP * 2) +
                               ((lane >> 3) & 1) * 16 + ks * 32);
                ldsm4(kf[nt], kBuf + ko);
            }
#pragma unroll
            for (int ni = 0; ni < 8; ni++)
                mma16816h(st[ni], qf[ks], &kf[ni >> 1][(ni & 1) * 2]);
        }

#pragma unroll
        for (int ni = 0; ni < 8; ni++)
#pragma unroll
            for (int e = 0; e < 4; e++) st[ni][e] *= 0.125f;
        if (kt == qt) {
#pragma unroll
            for (int ni = 0; ni < 8; ni++) {
                int cb = ni * 8 + (lane & 3) * 2;
                if (cb > rl0)         st[ni][0] = -1e30f;
                if (cb + 1 > rl0)     st[ni][1] = -1e30f;
                if (cb > rl0 + 8)     st[ni][2] = -1e30f;
                if (cb + 1 > rl0 + 8) st[ni][3] = -1e30f;
            }
        }

        float t0 = -1e30f, t1 = -1e30f;
#pragma unroll
        for (int ni = 0; ni < 8; ni++) {
            t0 = fmaxf(t0, fmaxf(st[ni][0], st[ni][1]));
            t1 = fmaxf(t1, fmaxf(st[ni][2], st[ni][3]));
        }
        t0 = fmaxf(t0, __shfl_xor_sync(0xffffffffu, t0, 1));
        t0 = fmaxf(t0, __shfl_xor_sync(0xffffffffu, t0, 2));
        t1 = fmaxf(t1, __shfl_xor_sync(0xffffffffu, t1, 1));
        t1 = fmaxf(t1, __shfl_xor_sync(0xffffffffu, t1, 2));
        float mn0 = fmaxf(m_0, t0), mn1 = fmaxf(m_1, t1);
        float fr0 = __expf(m_0 - mn0), fr1 = __expf(m_1 - mn1);
        m_0 = mn0; m_1 = mn1;
        float ps0 = 0.f, ps1 = 0.f;
#pragma unroll
        for (int ni = 0; ni < 8; ni++) {
            float p0 = __expf(st[ni][0] - mn0); st[ni][0] = p0; ps0 += p0;
            float p1 = __expf(st[ni][1] - mn0); st[ni][1] = p1; ps0 += p1;
            float p2 = __expf(st[ni][2] - mn1); st[ni][2] = p2; ps1 += p2;
            float p3 = __expf(st[ni][3] - mn1); st[ni][3] = p3; ps1 += p3;
        }
        ps0 += __shfl_xor_sync(0xffffffffu, ps0, 1);
        ps0 += __shfl_xor_sync(0xffffffffu, ps0, 2);
        ps1 += __shfl_xor_sync(0xffffffffu, ps1, 1);
        ps1 += __shfl_xor_sync(0xffffffffu, ps1, 2);
        l_0 = l_0 * fr0 + ps0;
        l_1 = l_1 * fr1 + ps1;
#pragma unroll
        for (int ni = 0; ni < 8; ni++) {
            acc[ni][0] *= fr0; acc[ni][1] *= fr0;
            acc[ni][2] *= fr1; acc[ni][3] *= fr1;
        }

#pragma unroll
        for (int ks = 0; ks < 4; ks++) {
            uint32_t pa[4];
            pa[0] = pack_h2(st[2 * ks][0],     st[2 * ks][1]);
            pa[1] = pack_h2(st[2 * ks][2],     st[2 * ks][3]);
            pa[2] = pack_h2(st[2 * ks + 1][0], st[2 * ks + 1][1]);
            pa[3] = pack_h2(st[2 * ks + 1][2], st[2 * ks + 1][3]);
            uint32_t vf[4][4];
#pragma unroll
            for (int vt = 0; vt < 4; vt++) {
                uint32_t vo =
                    (uint32_t)(((lane & 7) + ((lane >> 3) & 1) * 8 + ks * 16) * (AP * 2) +
                               (vt * 16 + (lane >> 4) * 8) * 2);
                ldsm4t(vf[vt], vBuf + vo);
            }
#pragma unroll
            for (int ni = 0; ni < 8; ni++)
                mma16816h(acc[ni], pa, &vf[ni >> 1][(ni & 1) * 2]);
        }
        __syncthreads();
    }

    float i0 = 1.f / l_0, i1 = 1.f / l_1;
    const int r0 = q0 + rl0;
#pragma unroll
    for (int ni = 0; ni < 8; ni++) {
        int col = ni * 8 + (lane & 3) * 2;
        size_t o = base + (size_t)r0 * CD + col;
        *(uint32_t*)(At + o) = pack_h2(acc[ni][0] * i0, acc[ni][1] * i0);
        *(uint32_t*)(At + o + (size_t)8 * CD) =
            pack_h2(acc[ni][2] * i1, acc[ni][3] * i1);
    }
}

// ----------------------------------------------------------------------------
// Embedding / LayerNorm
// ----------------------------------------------------------------------------
__global__ void embed_kernel(const int* __restrict__ ids,
                             const float* __restrict__ tok,
                             const float* __restrict__ pos,
                             float* __restrict__ h) {
    int i = blockIdx.x;
    int d = threadIdx.x;
    int s = i & (CS - 1);
    h[(size_t)i * CD + d] = tok[(size_t)ids[i] * CD + d] + pos[(size_t)s * CD + d];
}

__global__ void ln_kernel(const float* __restrict__ x,
                          const float* __restrict__ sc,
                          const float* __restrict__ bi,
                          __half* __restrict__ yf) {
    int row = blockIdx.x * 8 + threadIdx.y;   // blockDim (32, 8)
    int lane = threadIdx.x;
    const float* xr = x + (size_t)row * CD;
    float v[8];
    float sum = 0.f, sq = 0.f;
#pragma unroll
    for (int j = 0; j < 8; j++) {
        v[j] = xr[lane * 8 + j];
        sum += v[j];
        sq += v[j] * v[j];
    }
#pragma unroll
    for (int o = 16; o > 0; o >>= 1) {
        sum += __shfl_xor_sync(0xffffffffu, sum, o);
        sq  += __shfl_xor_sync(0xffffffffu, sq, o);
    }
    float mean = sum * (1.f / CD);
    float var  = sq * (1.f / CD) - mean * mean;
    float inv  = rsqrtf(var + 1e-5f);
    size_t off = (size_t)row * CD + lane * 8;
    __half2 f[4];
#pragma unroll
    for (int j = 0; j < 4; j++) {
        int c = lane * 8 + 2 * j;
        float y0 = (v[2 * j]     - mean) * inv * sc[c]     + bi[c];
        float y1 = (v[2 * j + 1] - mean) * inv * sc[c + 1] + bi[c + 1];
        f[j] = __floats2half2_rn(y0, y1);
    }
    *(uint4*)(yf + off) = *(uint4*)f;
}

// ----------------------------------------------------------------------------
// Orchestration
// ----------------------------------------------------------------------------
extern "C" void kernel_launch(void* const* d_in, const int* in_sizes, int n_in,
                              void* d_out, int out_size) {
    const int*   ids  = (const int*)d_in[0];
    const float* tok  = (const float*)d_in[1];
    const float* pos  = (const float*)d_in[2];
    const float* Wq   = (const float*)d_in[3];
    const float* bq   = (const float*)d_in[4];
    const float* Wk   = (const float*)d_in[5];
    const float* bk   = (const float*)d_in[6];
    const float* Wv   = (const float*)d_in[7];
    const float* bv   = (const float*)d_in[8];
    const float* Wo   = (const float*)d_in[9];
    const float* bo   = (const float*)d_in[10];
    const float* ln1s = (const float*)d_in[11];
    const float* ln1b = (const float*)d_in[12];
    const float* ln2s = (const float*)d_in[13];
    const float* ln2b = (const float*)d_in[14];
    const float* W1   = (const float*)d_in[15];
    const float* b1   = (const float*)d_in[16];
    const float* W2   = (const float*)d_in[17];
    const float* b2   = (const float*)d_in[18];
    const float* lnfs = (const float*)d_in[19];
    const float* lnfb = (const float*)d_in[20];
    float* out = (float*)d_out;

    float* h;
    __half *n, *q, *k, *v, *att, *m, *tf, *wq, *wk, *wv, *wo, *w1, *w2;
    cudaGetSymbolAddress((void**)&h,   g_h);
    cudaGetSymbolAddress((void**)&n,   g_n);
    cudaGetSymbolAddress((void**)&q,   g_q);
    cudaGetSymbolAddress((void**)&k,   g_k);
    cudaGetSymbolAddress((void**)&v,   g_v);
    cudaGetSymbolAddress((void**)&att, g_att);
    cudaGetSymbolAddress((void**)&m,   g_m);
    cudaGetSymbolAddress((void**)&tf,  g_tf);
    cudaGetSymbolAddress((void**)&wq,  g_wq);
    cudaGetSymbolAddress((void**)&wk,  g_wk);
    cudaGetSymbolAddress((void**)&wv,  g_wv);
    cudaGetSymbolAddress((void**)&wo,  g_wo);
    cudaGetSymbolAddress((void**)&w1,  g_w1);
    cudaGetSymbolAddress((void**)&w2,  g_w2);

    cudaFuncSetAttribute(attn_kernel,
                         cudaFuncAttributeMaxDynamicSharedMemorySize, ATTN_SMEM);
    cudaFuncSetAttribute(gemm_res_kernel,
                         cudaFuncAttributeMaxDynamicSharedMemorySize, SMEM_RES);
    cudaFuncSetAttribute(gemm_gelu_kernel,
                         cudaFuncAttributeMaxDynamicSharedMemorySize, SMEM_BIG);
    cudaFuncSetAttribute(qkv_kernel,
                         cudaFuncAttributeMaxDynamicSharedMemorySize, SMEM_BIG);
    cudaFuncSetAttribute(lmhead_kernel,
                         cudaFuncAttributeMaxDynamicSharedMemorySize, SMEM_LMH);

    convert_all_kernel<<<(unsigned)((NP_TOT + 255) / 256), 256>>>(
        tok, Wq, Wk, Wv, Wo, W1, W2, tf, wq, wk, wv, wo, w1, w2);

    dim3 lnb(32, 8);
    embed_kernel<<<CM, CD>>>(ids, tok, pos, h);

    for (int l = 0; l < CL; l++) {
        size_t wofs  = (size_t)l * CD * CD;
        size_t bofs  = (size_t)l * CD;
        size_t w1ofs = (size_t)l * CD * CFF;
        size_t b1ofs = (size_t)l * CFF;
        size_t w2ofs = (size_t)l * CFF * CD;

        ln_kernel<<<CM / 8, lnb>>>(h, ln1s + bofs, ln1b + bofs, n);
        qkv_kernel<<<dim3(CD / 128, CM / 128, 3), 256, SMEM_BIG>>>(
            n, wq + wofs, wk + wofs, wv + wofs,
            bq + bofs, bk + bofs, bv + bofs, q, k, v);

        attn_kernel<<<dim3(CS / 64, CB * CH), 128, ATTN_SMEM>>>(q, k, v, att);

        gemm_res_kernel<<<dim3(CD / 64, CM / 128), 256, SMEM_RES>>>(
            att, wo + wofs, bo + bofs, h, h, CD, CD);

        ln_kernel<<<CM / 8, lnb>>>(h, ln2s + bofs, ln2b + bofs, n);
        gemm_gelu_kernel<<<dim3(CFF / 128, CM / 128), 256, SMEM_BIG>>>(
            n, w1 + w1ofs, b1 + b1ofs, m, CFF, CD);
        gemm_res_kernel<<<dim3(CD / 64, CM / 128), 256, SMEM_RES>>>(
            m, w2 + w2ofs, b2 + bofs, h, h, CD, CFF);
    }

    ln_kernel<<<CM / 8, lnb>>>(h, lnfs, lnfb, n);
    lmhead_kernel<<<dim3(CM / 128, (CV + 127) / 128), 256, SMEM_LMH>>>(
        n, tf, out);
}